// round 7
// baseline (speedup 1.0000x reference)
#include <cuda_runtime.h>

#define BB 32
#define LL 8192
#define DD 256
#define MM (LL/2 + 1)                         // 4097
#define NS (BB * LL / 32)                     // 8192 score blocks (32 rows each)
#define NC BB                                 // 32 compact blocks
#define TOTAL4 ((long long)BB * MM * (DD/4))  // 8,390,656 vec4s
#define NG ((int)(TOTAL4 / 256))              // 32776 gather blocks (exact)
#define OUT_ELEMS ((long long)BB * MM * DD)

// Scratch (no device allocation allowed)
__device__ float g_s[BB * LL];
__device__ int   g_starts[BB * MM];
__device__ int   g_counts[BB * 32];           // stride 32 ints = 128B (own L1 line per batch)
__device__ int   g_done[BB];                  // score-blocks-finished counter per batch
__device__ volatile int g_flag[BB];           // compact-finished flag per batch

// ---------------------------------------------------------------------------
__global__ void init_kernel() {
    int i = threadIdx.x;
    if (i < BB) { g_done[i] = 0; g_flag[i] = 0; }
}

// ---------------------------------------------------------------------------
// One kernel, three bid-ordered phases. HW dispatches CTAs in bid order, so
// every spin-wait's producers have strictly lower bids (already dispatched).
// ---------------------------------------------------------------------------
__global__ void __launch_bounds__(256) fused_kernel(
    const float* __restrict__ x, const float* __restrict__ W,
    const float* __restrict__ bias, float* __restrict__ out, int write_counts)
{
    int bid = blockIdx.x;
    int tid = threadIdx.x;
    int lane = tid & 31, warp = tid >> 5;

    if (bid < NS) {
        // ================= PHASE 1: scores (32 rows per block) =============
        __shared__ __align__(16) float sW[DD];
        sW[tid] = W[tid];
        __syncthreads();

        long long row0 = (long long)bid * 32 + warp * 4;   // 4 rows per warp
        const float4* wv = (const float4*)sW;
        float4 w0 = wv[lane];
        float4 w1 = wv[lane + 32];
        float bv = bias[0];

        float4 v0[4], v1[4];                 // front-batched: 8 LDG.128 in flight
#pragma unroll
        for (int r = 0; r < 4; r++) {
            const float4* src = (const float4*)(x + (row0 + r) * DD);
            v0[r] = __ldcs(src + lane);
            v1[r] = __ldcs(src + lane + 32);
        }
        float acc[4];
#pragma unroll
        for (int r = 0; r < 4; r++) {
            acc[r] = v0[r].x*w0.x + v0[r].y*w0.y + v0[r].z*w0.z + v0[r].w*w0.w
                   + v1[r].x*w1.x + v1[r].y*w1.y + v1[r].z*w1.z + v1[r].w*w1.w;
        }
#pragma unroll
        for (int o = 16; o; o >>= 1) {
#pragma unroll
            for (int r = 0; r < 4; r++)
                acc[r] += __shfl_xor_sync(0xffffffffu, acc[r], o);
        }
        if (lane == 0) {
            float4 s4;
            s4.x = 1.f / (1.f + expf(-(acc[0] + bv)));
            s4.y = 1.f / (1.f + expf(-(acc[1] + bv)));
            s4.z = 1.f / (1.f + expf(-(acc[2] + bv)));
            s4.w = 1.f / (1.f + expf(-(acc[3] + bv)));
            *(float4*)(g_s + row0) = s4;
            __threadfence();                  // release this warp's s-store
        }
        __syncthreads();
        if (tid == 0) atomicAdd(&g_done[bid >> 8], 1);   // batch = bid/256

    } else if (bid < NS + NC) {
        // ================= PHASE 2: per-batch compaction ===================
        int b = bid - NS;
        if (tid == 0) {
            while (((volatile int*)g_done)[b] != 256) __nanosleep(64);
        }
        __syncthreads();
        __threadfence();                      // acquire

        const float* s = g_s + (long long)b * LL;
        int base = tid * 32;                  // 32 positions per thread
        float prev = (base > 0) ? s[base - 1] : 0.f;
        float cur = s[base];
        unsigned mb = 0;
#pragma unroll 4
        for (int i = 0; i < 32; i++) {
            int l = base + i;
            float nxt = (l + 1 < LL) ? s[l + 1] : 0.f;
            bool m = (l == 0) ? true
                   : ((l >= LL - 1) ? false : (cur < prev && cur < nxt));
            mb |= (m ? 1u : 0u) << i;
            prev = cur; cur = nxt;
        }
        int cnt = __popc(mb);

        // block exclusive scan of per-thread counts
        int v = cnt;
#pragma unroll
        for (int o = 1; o < 32; o <<= 1) {
            int t = __shfl_up_sync(0xffffffffu, v, o);
            if (lane >= o) v += t;
        }
        __shared__ int ws[8];
        __shared__ int s_tot;
        if (lane == 31) ws[warp] = v;
        __syncthreads();
        if (tid == 0) {
            int run = 0;
#pragma unroll
            for (int w = 0; w < 8; w++) { int t = ws[w]; ws[w] = run; run += t; }
            s_tot = run;
        }
        __syncthreads();

        int off = ws[warp] + (v - cnt);
        int* st = g_starts + (long long)b * MM;
        unsigned t = mb;
        while (t) { int i = __ffs(t) - 1; t &= t - 1; st[off++] = base + i; }

        __threadfence();                      // release starts
        __syncthreads();
        if (tid == 0) {
            int total = s_tot;
            g_counts[b * 32] = total;
            if (write_counts) out[OUT_ELEMS + b] = (float)total;
            __threadfence();
            atomicExch((int*)&g_flag[b], 1);  // publish
        }

    } else {
        // ================= PHASE 3: gather (4 output rows per block) =======
        int g = bid - NS - NC;
        long long idx = (long long)g * 256 + tid;          // vec4 index
        int rf = g * 4, rl = g * 4 + 3;                    // rows this block touches
        int bf = rf / MM, bl = rl / MM;
        if (tid == 0) {
            while (g_flag[bf] == 0 || g_flag[bl] == 0) __nanosleep(64);
        }
        __syncthreads();
        __threadfence();                      // acquire

        long long row = idx >> 6;             // b*MM + k
        int j = (int)(idx & 63);
        int b = (int)(row / MM);
        int k = (int)(row - (long long)b * MM);
        int cnt = __ldcg(&g_counts[b * 32]);

        float4 o;
        if (k >= cnt) {
            o.x = 0.f; o.y = 0.f; o.z = 0.f; o.w = 0.f;
        } else {
            int p = g_starts[row];            // valley start; p+1 < LL guaranteed
            long long xrow = (long long)b * LL + p;
            float s0 = g_s[xrow];
            float s1 = g_s[xrow + 1];
            float rden = 1.f / fmaxf(s0 + s1, 1e-6f);
            float a0 = s0 * rden, a1 = s1 * rden;

            const float4* x0 = (const float4*)(x + xrow * DD);
            float4 q0 = __ldcs(x0 + j);
            float4 q1 = __ldcs(x0 + (DD / 4) + j);
            o.x = a0 * q0.x + a1 * q1.x;
            o.y = a0 * q0.y + a1 * q1.y;
            o.z = a0 * q0.z + a1 * q1.z;
            o.w = a0 * q0.w + a1 * q1.w;
        }
        __stcs((float4*)out + idx, o);
    }
}

// ---------------------------------------------------------------------------
extern "C" void kernel_launch(void* const* d_in, const int* in_sizes, int n_in,
                              void* d_out, int out_size) {
    const float* x    = (const float*)d_in[0];   // [B, L, D] f32
    // d_in[1]: olens (unused by the reference computation)
    const float* W    = (const float*)d_in[2];   // [D, 1] f32
    const float* bias = (const float*)d_in[3];   // [1] f32

    float* out = (float*)d_out;
    int write_counts = (out_size >= (int)(OUT_ELEMS + BB)) ? 1 : 0;

    init_kernel<<<1, 32>>>();
    fused_kernel<<<NS + NC + NG, 256>>>(x, W, bias, out, write_counts);
}

// round 8
// speedup vs baseline: 1.2765x; 1.2765x over previous
#include <cuda_runtime.h>

#define BB 32
#define LL 8192
#define DD 256
#define MM (LL/2 + 1)             // 4097
#define CH 64                     // rows per chunk
#define CHUNKS (LL / CH)          // 128
#define NBLK (BB * CHUNKS)        // 4096
#define OUT_ELEMS ((long long)BB * MM * DD)
#define SX_ROWS (CH + 1)          // 65 rows resident (chunk + next-row halo)
#define SMEM_BYTES (SX_ROWS * DD * 4)   // 66,560 B dynamic smem

// Scratch (no device allocation allowed)
__device__ unsigned long long g_state[NBLK];   // lookback: flag<<32 | count
__device__ int g_counts[BB];

// ---------------------------------------------------------------------------
__global__ void init_kernel() {
    int i = blockIdx.x * blockDim.x + threadIdx.x;
    if (i < NBLK) g_state[i] = 0ull;
}

// ---------------------------------------------------------------------------
// Single pass: each block owns 64 rows of one batch. Loads them (+1 halo row)
// into SMEM while computing the 66 sigmoid scores it needs, finds strict local
// minima, resolves its global output offset via warp-parallel windowed
// lookback (single-word atomics, no fences), then writes pooled rows straight
// from SMEM. x is read exactly once (+3% halo); no intermediate s array.
// ---------------------------------------------------------------------------
__global__ void __launch_bounds__(256) fused_kernel(
    const float* __restrict__ x, const float* __restrict__ W,
    const float* __restrict__ bias, float* __restrict__ out, int write_counts)
{
    extern __shared__ __align__(16) float sx[];     // [SX_ROWS][DD]
    __shared__ __align__(16) float sW[DD];
    __shared__ float ss[CH + 2];                    // s for rows r0-1 .. r0+CH
    __shared__ int s_list[CH/2 + 4];
    __shared__ int s_cnt[2];
    __shared__ int s_tot, s_ex;

    int tid = threadIdx.x, lane = tid & 31, warp = tid >> 5;
    int bid = blockIdx.x;
    int b = bid >> 7;                 // bid / CHUNKS
    int c = bid & (CHUNKS - 1);
    int r0 = c * CH;

    sW[tid] = W[tid];
    __syncthreads();

    const float4* wv = (const float4*)sW;
    float4 w0 = wv[lane], w1 = wv[lane + 32];
    float bv = bias[0];
    const float* xb = x + (long long)b * LL * DD;
    float4* sx4 = (float4*)sx;

    // --- dot tasks j=0..65: global row gr = r0 + j - 1; rows j>=1 kept in SMEM.
    //     two tasks per iteration for MLP (4 LDG.128 in flight per thread).
    for (int j = warp; j < CH + 2; j += 16) {
        int ja = j, jb = j + 8;
        int gra = r0 + ja - 1, grb = r0 + jb - 1;
        bool va = (gra >= 0) && (gra < LL);
        bool vb = (jb < CH + 2) && (grb < LL);
        float4 a0, a1, c0, c1;
        if (va) {
            const float4* s_ = (const float4*)(xb + (long long)gra * DD);
            a0 = __ldcs(s_ + lane); a1 = __ldcs(s_ + lane + 32);
        }
        if (vb) {
            const float4* s_ = (const float4*)(xb + (long long)grb * DD);
            c0 = __ldcs(s_ + lane); c1 = __ldcs(s_ + lane + 32);
        }
        float accA = 0.f, accB = 0.f;
        if (va) {
            if (ja >= 1) {
                sx4[(ja - 1) * 64 + lane] = a0;
                sx4[(ja - 1) * 64 + 32 + lane] = a1;
            }
            accA = a0.x*w0.x + a0.y*w0.y + a0.z*w0.z + a0.w*w0.w
                 + a1.x*w1.x + a1.y*w1.y + a1.z*w1.z + a1.w*w1.w;
        }
        if (vb) {
            sx4[(jb - 1) * 64 + lane] = c0;
            sx4[(jb - 1) * 64 + 32 + lane] = c1;
            accB = c0.x*w0.x + c0.y*w0.y + c0.z*w0.z + c0.w*w0.w
                 + c1.x*w1.x + c1.y*w1.y + c1.z*w1.z + c1.w*w1.w;
        }
#pragma unroll
        for (int o = 16; o; o >>= 1) {
            accA += __shfl_xor_sync(0xffffffffu, accA, o);
            accB += __shfl_xor_sync(0xffffffffu, accB, o);
        }
        if (lane == 0) {
            ss[ja] = va ? (1.f / (1.f + expf(-(accA + bv)))) : 0.f;
            if (jb < CH + 2) ss[jb] = vb ? (1.f / (1.f + expf(-(accB + bv)))) : 0.f;
        }
    }
    __syncthreads();

    // --- strict-local-minima mask over the 64 owned positions (warps 0,1) ---
    bool m = false; int pfx = 0;
    if (tid < CH) {
        int l = r0 + tid;
        float cc = ss[tid + 1];
        m = (l == 0) ? true
          : ((l >= LL - 1) ? false : (cc < ss[tid] && cc < ss[tid + 2]));
        unsigned bits = __ballot_sync(0xffffffffu, m);
        pfx = __popc(bits & ((1u << lane) - 1));
        if (lane == 0) s_cnt[warp] = __popc(bits);
    }
    __syncthreads();
    if (tid == 0) s_tot = s_cnt[0] + s_cnt[1];
    if (tid < CH && m) {
        int off = (warp == 1) ? s_cnt[0] : 0;
        s_list[off + pfx] = tid;
    }
    __syncthreads();

    // --- warp-parallel windowed lookback (warp 0) ---
    if (warp == 0) {
        int tot = s_tot;
        long long ex = 0;
        if (c != 0) {
            if (lane == 0)
                atomicExch(&g_state[bid], (1ull << 32) | (unsigned)tot);  // AGG
            __syncwarp();
            int begin = b * CHUNKS;
            int base = bid - 1;
            for (;;) {
                int i = base - lane;
                unsigned long long v;
                if (i >= begin) {
                    volatile unsigned long long* p =
                        (volatile unsigned long long*)&g_state[i];
                    do { v = *p; } while ((unsigned)(v >> 32) == 0u);
                } else {
                    v = (2ull << 32);                 // virtual prefix 0
                }
                unsigned pm = __ballot_sync(0xffffffffu, (unsigned)(v >> 32) == 2u);
                long long contrib;
                if (pm) {
                    int cut = __ffs(pm) - 1;          // nearest PREFIX
                    contrib = (lane <= cut) ? (long long)(unsigned)v : 0;
                } else {
                    contrib = (long long)(unsigned)v; // all AGG: take them all
                }
#pragma unroll
                for (int o = 16; o; o >>= 1)
                    contrib += __shfl_xor_sync(0xffffffffu, contrib, o);
                ex += contrib;
                if (pm) break;
                base -= 32;
            }
        }
        if (lane == 0) {
            atomicExch(&g_state[bid], (2ull << 32) | (unsigned)(ex + tot)); // PREFIX
            s_ex = (int)ex;
            if (c == CHUNKS - 1) {
                int tb = (int)ex + tot;
                g_counts[b] = tb;
                if (write_counts) out[OUT_ELEMS + b] = (float)tb;
            }
        }
    }
    __syncthreads();

    // --- emit pooled rows from SMEM: 4 rows in parallel, 64 threads/row ---
    int ex = s_ex, tot = s_tot;
    int grp = tid >> 6, col = tid & 63;
    for (int j0 = grp; j0 < tot; j0 += 4) {
        int t = s_list[j0];                 // local valley index; t+1 row resident
        float s0 = ss[t + 1], s1 = ss[t + 2];
        float rden = 1.f / fmaxf(s0 + s1, 1e-6f);
        float a0 = s0 * rden, a1 = s1 * rden;
        float4 v0 = sx4[t * 64 + col];
        float4 v1 = sx4[(t + 1) * 64 + col];
        float4 o;
        o.x = a0 * v0.x + a1 * v1.x;
        o.y = a0 * v0.y + a1 * v1.y;
        o.z = a0 * v0.z + a1 * v1.z;
        o.w = a0 * v0.w + a1 * v1.w;
        __stcs((float4*)out + ((long long)b * MM + ex + j0) * 64 + col, o);
    }
}

// ---------------------------------------------------------------------------
// Zero the sentinel tail rows [count_b, MM) of each batch.
// ---------------------------------------------------------------------------
__global__ void __launch_bounds__(256) zero_tail_kernel(float* __restrict__ out) {
    long long idx = (long long)blockIdx.x * blockDim.x + threadIdx.x;
    long long row = idx >> 6;
    int b = (int)(row / MM);
    int k = (int)(row - (long long)b * MM);
    if (k >= g_counts[b]) {
        float4 z; z.x = 0.f; z.y = 0.f; z.z = 0.f; z.w = 0.f;
        __stcs((float4*)out + idx, z);
    }
}

// ---------------------------------------------------------------------------
extern "C" void kernel_launch(void* const* d_in, const int* in_sizes, int n_in,
                              void* d_out, int out_size) {
    const float* x    = (const float*)d_in[0];   // [B, L, D] f32
    // d_in[1]: olens (unused by the reference computation)
    const float* W    = (const float*)d_in[2];   // [D, 1] f32
    const float* bias = (const float*)d_in[3];   // [1] f32

    float* out = (float*)d_out;
    int write_counts = (out_size >= (int)(OUT_ELEMS + BB)) ? 1 : 0;

    cudaFuncSetAttribute(fused_kernel,
                         cudaFuncAttributeMaxDynamicSharedMemorySize, SMEM_BYTES);

    init_kernel<<<(NBLK + 255) / 256, 256>>>();
    fused_kernel<<<NBLK, 256, SMEM_BYTES>>>(x, W, bias, out, write_counts);
    {
        long long total4 = (long long)BB * MM * (DD / 4);   // 8,390,656
        int grid = (int)(total4 / 256);                     // exact: 32776
        zero_tail_kernel<<<grid, 256>>>(out);
    }
}

// round 10
// speedup vs baseline: 1.3315x; 1.0431x over previous
#include <cuda_runtime.h>

#define BB 32
#define LL 8192
#define DD 256
#define MM (LL/2 + 1)             // 4097
#define CH 64                     // rows per chunk
#define CHUNKS (LL / CH)          // 128
#define NBLK (BB * CHUNKS)        // 4096
#define OUT_ELEMS ((long long)BB * MM * DD)
#define SX_ROWS (CH + 1)          // 65 rows resident (chunk + next-row halo)
#define SMEM_BYTES (SX_ROWS * DD * 4)   // 66,560 B dynamic smem
#define NT 512                    // threads per fused block

// Scratch (no device allocation allowed; zero-initialized at module load,
// re-zeroed by finish_kernel each call)
__device__ unsigned long long g_state[NBLK];   // lookback: flag<<32 | count
__device__ int g_counts[BB];

// ---------------------------------------------------------------------------
// Single pass: each block owns 64 rows of one batch. Loads them (+1 halo row)
// into SMEM while computing the 66 sigmoid scores it needs, finds strict local
// minima, resolves its global output offset via warp-parallel windowed
// lookback (single-word atomics), then writes pooled rows straight from SMEM.
// x is read exactly once (+3% halo); no intermediate s array in DRAM.
// ---------------------------------------------------------------------------
__global__ void __launch_bounds__(NT) fused_kernel(
    const float* __restrict__ x, const float* __restrict__ W,
    const float* __restrict__ bias, float* __restrict__ out, int write_counts)
{
    extern __shared__ __align__(16) float sx[];     // [SX_ROWS][DD]
    __shared__ __align__(16) float sW[DD];
    __shared__ float ss[CH + 2];                    // s for rows r0-1 .. r0+CH
    __shared__ int s_list[CH/2 + 4];
    __shared__ int s_cnt[2];
    __shared__ int s_tot, s_ex;

    int tid = threadIdx.x, lane = tid & 31, warp = tid >> 5;   // 16 warps
    int bid = blockIdx.x;
    int b = bid >> 7;                 // bid / CHUNKS
    int c = bid & (CHUNKS - 1);
    int r0 = c * CH;

    if (tid < DD) sW[tid] = W[tid];
    __syncthreads();

    const float4* wv = (const float4*)sW;
    float4 w0 = wv[lane], w1 = wv[lane + 32];
    float bv = bias[0];
    const float* xb = x + (long long)b * LL * DD;
    float4* sx4 = (float4*)sx;

    // --- dot tasks j=0..65: global row gr = r0 + j - 1; rows j>=1 kept in SMEM.
    //     16 warps, two tasks per iteration (4 LDG.128 in flight per thread),
    //     3 iterations total.
    for (int j = warp; j < CH + 2; j += 32) {
        int ja = j, jb = j + 16;
        int gra = r0 + ja - 1, grb = r0 + jb - 1;
        bool va = (gra >= 0) && (gra < LL);
        bool vb = (jb < CH + 2) && (grb < LL);
        float4 a0, a1, c0, c1;
        if (va) {
            const float4* s_ = (const float4*)(xb + (long long)gra * DD);
            a0 = __ldcs(s_ + lane); a1 = __ldcs(s_ + lane + 32);
        }
        if (vb) {
            const float4* s_ = (const float4*)(xb + (long long)grb * DD);
            c0 = __ldcs(s_ + lane); c1 = __ldcs(s_ + lane + 32);
        }
        float accA = 0.f, accB = 0.f;
        if (va) {
            if (ja >= 1) {
                sx4[(ja - 1) * 64 + lane] = a0;
                sx4[(ja - 1) * 64 + 32 + lane] = a1;
            }
            accA = a0.x*w0.x + a0.y*w0.y + a0.z*w0.z + a0.w*w0.w
                 + a1.x*w1.x + a1.y*w1.y + a1.z*w1.z + a1.w*w1.w;
        }
        if (vb) {
            sx4[(jb - 1) * 64 + lane] = c0;
            sx4[(jb - 1) * 64 + 32 + lane] = c1;
            accB = c0.x*w0.x + c0.y*w0.y + c0.z*w0.z + c0.w*w0.w
                 + c1.x*w1.x + c1.y*w1.y + c1.z*w1.z + c1.w*w1.w;
        }
#pragma unroll
        for (int o = 16; o; o >>= 1) {
            accA += __shfl_xor_sync(0xffffffffu, accA, o);
            accB += __shfl_xor_sync(0xffffffffu, accB, o);
        }
        if (lane == 0) {
            ss[ja] = va ? (1.f / (1.f + expf(-(accA + bv)))) : 0.f;
            if (jb < CH + 2) ss[jb] = vb ? (1.f / (1.f + expf(-(accB + bv)))) : 0.f;
        }
    }
    __syncthreads();

    // --- strict-local-minima mask over the 64 owned positions (warps 0,1) ---
    bool m = false; int pfx = 0;
    if (tid < CH) {
        int l = r0 + tid;
        float cc = ss[tid + 1];
        m = (l == 0) ? true
          : ((l >= LL - 1) ? false : (cc < ss[tid] && cc < ss[tid + 2]));
        unsigned bits = __ballot_sync(0xffffffffu, m);
        pfx = __popc(bits & ((1u << lane) - 1));
        if (lane == 0) s_cnt[warp] = __popc(bits);
    }
    __syncthreads();
    if (tid == 0) s_tot = s_cnt[0] + s_cnt[1];
    if (tid < CH && m) {
        int off = (warp == 1) ? s_cnt[0] : 0;
        s_list[off + pfx] = tid;
    }
    __syncthreads();

    // --- warp-parallel windowed lookback (warp 0) ---
    if (warp == 0) {
        int tot = s_tot;
        long long ex = 0;
        if (c != 0) {
            if (lane == 0)
                atomicExch(&g_state[bid], (1ull << 32) | (unsigned)tot);  // AGG
            __syncwarp();
            int begin = b * CHUNKS;
            int base = bid - 1;
            for (;;) {
                int i = base - lane;
                unsigned long long v;
                if (i >= begin) {
                    volatile unsigned long long* p =
                        (volatile unsigned long long*)&g_state[i];
                    v = *p;
                    while ((unsigned)(v >> 32) == 0u) { __nanosleep(32); v = *p; }
                } else {
                    v = (2ull << 32);                 // virtual prefix 0
                }
                unsigned pm = __ballot_sync(0xffffffffu, (unsigned)(v >> 32) == 2u);
                long long contrib;
                if (pm) {
                    int cut = __ffs(pm) - 1;          // nearest PREFIX
                    contrib = (lane <= cut) ? (long long)(unsigned)v : 0;
                } else {
                    contrib = (long long)(unsigned)v; // all AGG: take them all
                }
#pragma unroll
                for (int o = 16; o; o >>= 1)
                    contrib += __shfl_xor_sync(0xffffffffu, contrib, o);
                ex += contrib;
                if (pm) break;
                base -= 32;
            }
        }
        if (lane == 0) {
            atomicExch(&g_state[bid], (2ull << 32) | (unsigned)(ex + tot)); // PREFIX
            s_ex = (int)ex;
            if (c == CHUNKS - 1) {
                int tb = (int)ex + tot;
                g_counts[b] = tb;
                if (write_counts) out[OUT_ELEMS + b] = (float)tb;
            }
        }
    }
    __syncthreads();

    // --- emit pooled rows from SMEM: 8 rows in parallel, 64 threads/row ---
    int ex = s_ex, tot = s_tot;
    int grp = tid >> 6, col = tid & 63;
    for (int j0 = grp; j0 < tot; j0 += 8) {
        int t = s_list[j0];                 // local valley index; t+1 row resident
        float s0 = ss[t + 1], s1 = ss[t + 2];
        float rden = 1.f / fmaxf(s0 + s1, 1e-6f);
        float a0 = s0 * rden, a1 = s1 * rden;
        float4 v0 = sx4[t * 64 + col];
        float4 v1 = sx4[(t + 1) * 64 + col];
        float4 o;
        o.x = a0 * v0.x + a1 * v1.x;
        o.y = a0 * v0.y + a1 * v1.y;
        o.z = a0 * v0.z + a1 * v1.z;
        o.w = a0 * v0.w + a1 * v1.w;
        __stcs((float4*)out + ((long long)b * MM + ex + j0) * 64 + col, o);
    }
}

// ---------------------------------------------------------------------------
// Finish: zero the sentinel tail rows [count_b, MM) of each batch AND reset
// g_state for the next invocation (keeps kernel_launch deterministic).
// ---------------------------------------------------------------------------
__global__ void __launch_bounds__(256) finish_kernel(float* __restrict__ out) {
    long long idx = (long long)blockIdx.x * blockDim.x + threadIdx.x;
    if (idx < NBLK) g_state[idx] = 0ull;          // reset for next call

    long long row = idx >> 6;
    int b = (int)(row / MM);
    int k = (int)(row - (long long)b * MM);
    if (k >= g_counts[b]) {
        float4 z; z.x = 0.f; z.y = 0.f; z.z = 0.f; z.w = 0.f;
        __stcs((float4*)out + idx, z);
    }
}

// ---------------------------------------------------------------------------
extern "C" void kernel_launch(void* const* d_in, const int* in_sizes, int n_in,
                              void* d_out, int out_size) {
    const float* x    = (const float*)d_in[0];   // [B, L, D] f32
    // d_in[1]: olens (unused by the reference computation)
    const float* W    = (const float*)d_in[2];   // [D, 1] f32
    const float* bias = (const float*)d_in[3];   // [1] f32

    float* out = (float*)d_out;
    int write_counts = (out_size >= (int)(OUT_ELEMS + BB)) ? 1 : 0;

    cudaFuncSetAttribute(fused_kernel,
                         cudaFuncAttributeMaxDynamicSharedMemorySize, SMEM_BYTES);

    fused_kernel<<<NBLK, NT, SMEM_BYTES>>>(x, W, bias, out, write_counts);
    {
        long long total4 = (long long)BB * MM * (DD / 4);   // 8,390,656
        int grid = (int)(total4 / 256);                     // exact: 32776
        finish_kernel<<<grid, 256>>>(out);
    }
}